// round 2
// baseline (speedup 1.0000x reference)
#include <cuda_runtime.h>
#include <cuda_bf16.h>

// Problem constants (fixed by the reference)
#define N_NODES 20000
#define N_EDGES 200000
#define N_SEG   16
#define EXTENT  32
#define N_PATHS 64
#define OP_SIZE (N_SEG * EXTENT)   // 512

// Path metadata sorted by output segment (i3), built once per launch by prep kernel.
__device__ int   g_seg_start[N_SEG + 1];
__device__ int   g_path_i1[N_PATHS];
__device__ int   g_path_i2[N_PATHS];
__device__ float g_path_c[N_PATHS];

// Single-thread prep: counting-sort the 64 paths by their output segment i3.
// NOTE: jax downgrades int64 -> int32 (x64 disabled), so indices are int32.
__global__ void prep_paths_kernel(const int* __restrict__ path_indices,
                                  const float* __restrict__ path_coeffs) {
    if (threadIdx.x != 0 || blockIdx.x != 0) return;
    int cnt[N_SEG];
#pragma unroll
    for (int s = 0; s < N_SEG; s++) cnt[s] = 0;
    for (int p = 0; p < N_PATHS; p++) {
        int s = path_indices[p * 3 + 2];
        cnt[s]++;
    }
    int start[N_SEG + 1];
    start[0] = 0;
#pragma unroll
    for (int s = 0; s < N_SEG; s++) start[s + 1] = start[s] + cnt[s];
    for (int s = 0; s <= N_SEG; s++) g_seg_start[s] = start[s];
    int pos[N_SEG];
#pragma unroll
    for (int s = 0; s < N_SEG; s++) pos[s] = start[s];
    for (int p = 0; p < N_PATHS; p++) {
        int s   = path_indices[p * 3 + 2];
        int idx = pos[s]++;
        g_path_i1[idx] = path_indices[p * 3 + 0];
        g_path_i2[idx] = path_indices[p * 3 + 1];
        g_path_c[idx]  = path_coeffs[p];
    }
}

// One block per edge. 512 threads = 16 segments (warps) x 32 extent (lanes).
// Stage x1 = x_nodes[src[e]] and x2 = x_edges[e] in shared, then each warp
// accumulates its segment's paths and does one no-return atomicAdd per element.
__global__ __launch_bounds__(OP_SIZE, 4)
void seg_poly_kernel(const float* __restrict__ x_nodes,
                     const float* __restrict__ x_edges,
                     const int* __restrict__ src,
                     const int* __restrict__ dst,
                     float* __restrict__ out) {
    __shared__ float s_x1[OP_SIZE];
    __shared__ float s_x2[OP_SIZE];
    __shared__ int   s_i1[N_PATHS];
    __shared__ int   s_i2[N_PATHS];
    __shared__ float s_c[N_PATHS];
    __shared__ int   s_start[N_SEG + 1];
    __shared__ int   s_dst;

    const int e = blockIdx.x;
    const int t = threadIdx.x;

    // Coalesced stage of both 512-float rows.
    const int se = src[e];
    s_x1[t] = x_nodes[(long long)se * OP_SIZE + t];
    s_x2[t] = x_edges[(long long)e * OP_SIZE + t];

    if (t < N_PATHS) {
        s_i1[t] = g_path_i1[t];
        s_i2[t] = g_path_i2[t];
        s_c[t]  = g_path_c[t];
    }
    if (t <= N_SEG) s_start[t] = g_seg_start[t];
    if (t == 0) s_dst = dst[e];
    __syncthreads();

    const int seg  = t >> 5;
    const int lane = t & 31;

    const int j0 = s_start[seg];
    const int j1 = s_start[seg + 1];

    float acc = 0.0f;
    for (int j = j0; j < j1; j++) {
        // Conflict-free: within a warp, lane indexes consecutive addresses.
        acc = fmaf(s_c[j] * s_x1[s_i1[j] * EXTENT + lane],
                   s_x2[s_i2[j] * EXTENT + lane], acc);
    }

    if (j1 > j0) {
        // Unused return -> REDG (no-return atomic), spread addresses.
        atomicAdd(&out[(long long)s_dst * OP_SIZE + t], acc);
    }
    // Segments with no paths contribute exactly 0 -> output stays at the
    // memset zero, matching the reference.
}

extern "C" void kernel_launch(void* const* d_in, const int* in_sizes, int n_in,
                              void* d_out, int out_size) {
    const float* x_nodes      = (const float*)d_in[0];
    const float* x_edges      = (const float*)d_in[1];
    const float* path_coeffs  = (const float*)d_in[2];
    const int*   src          = (const int*)d_in[3];
    const int*   dst          = (const int*)d_in[4];
    const int*   path_indices = (const int*)d_in[5];
    float* out = (float*)d_out;

    // Output is poisoned 0xAA by the harness; zero it (graph-capturable).
    cudaMemsetAsync(out, 0, (size_t)N_NODES * OP_SIZE * sizeof(float));

    prep_paths_kernel<<<1, 32>>>(path_indices, path_coeffs);

    seg_poly_kernel<<<N_EDGES, OP_SIZE>>>(x_nodes, x_edges, src, dst, out);
}

// round 3
// speedup vs baseline: 2.4484x; 2.4484x over previous
#include <cuda_runtime.h>
#include <cuda_bf16.h>

// Problem constants (fixed by the reference)
#define N_NODES 20000
#define N_EDGES 200000
#define N_SEG   16
#define EXTENT  32
#define N_PATHS 64
#define OP_SIZE (N_SEG * EXTENT)   // 512
#define EPB     4                  // edges per block (200000 % 4 == 0)

// Path metadata sorted by output segment (i3), built by prep kernel.
// meta.x = i1*EXTENT*4 (byte offset), meta.y = i2*EXTENT*4, meta.z = coeff bits.
__device__ int4 g_meta[N_PATHS];
__device__ int  g_seg_start[N_SEG + 1];

// Single-thread prep: counting-sort the 64 paths by output segment i3 and
// precompute shared-memory byte offsets. Indices arrive as int32 (jax x64 off).
__global__ void prep_paths_kernel(const int* __restrict__ path_indices,
                                  const float* __restrict__ path_coeffs) {
    if (threadIdx.x != 0 || blockIdx.x != 0) return;
    int cnt[N_SEG];
#pragma unroll
    for (int s = 0; s < N_SEG; s++) cnt[s] = 0;
    for (int p = 0; p < N_PATHS; p++) cnt[path_indices[p * 3 + 2]]++;
    int start[N_SEG + 1];
    start[0] = 0;
#pragma unroll
    for (int s = 0; s < N_SEG; s++) start[s + 1] = start[s] + cnt[s];
    for (int s = 0; s <= N_SEG; s++) g_seg_start[s] = start[s];
    int pos[N_SEG];
#pragma unroll
    for (int s = 0; s < N_SEG; s++) pos[s] = start[s];
    for (int p = 0; p < N_PATHS; p++) {
        int s   = path_indices[p * 3 + 2];
        int idx = pos[s]++;
        int4 m;
        m.x = path_indices[p * 3 + 0] * (EXTENT * 4);
        m.y = path_indices[p * 3 + 1] * (EXTENT * 4);
        m.z = __float_as_int(path_coeffs[p]);
        m.w = 0;
        g_meta[idx] = m;
    }
}

// 4 edges per block. 512 threads = 16 segments (warps) x 32 extent (lanes);
// each thread carries 4 independent accumulators (one per edge).
__global__ __launch_bounds__(OP_SIZE)
void seg_poly_kernel(const float* __restrict__ x_nodes,
                     const float* __restrict__ x_edges,
                     const int* __restrict__ src,
                     const int* __restrict__ dst,
                     float* __restrict__ out) {
    __shared__ float s_x1[EPB * OP_SIZE];   // 8 KB
    __shared__ float s_x2[EPB * OP_SIZE];   // 8 KB
    __shared__ int4  s_meta[N_PATHS];
    __shared__ int   s_start[N_SEG + 1];
    __shared__ int   s_dst[EPB];

    const int e0 = blockIdx.x * EPB;
    const int t  = threadIdx.x;

    // Stage x_edges rows e0..e0+3: 2048 contiguous floats -> one float4/thread.
    ((float4*)s_x2)[t] = ((const float4*)(x_edges + (size_t)e0 * OP_SIZE))[t];

    // Stage x_nodes rows src[e0..e0+3]: 128 threads per row, float4 each.
    {
        const int r = t >> 7;        // which edge in the block
        const int q = t & 127;       // float4 index within the 512-float row
        const int sr = src[e0 + r];  // broadcast LDG, L1-cached
        ((float4*)s_x1)[t] = ((const float4*)(x_nodes + (size_t)sr * OP_SIZE))[q];
    }

    if (t < N_PATHS) s_meta[t] = g_meta[t];
    if (t <= N_SEG)  s_start[t] = g_seg_start[t];
    if (t < EPB)     s_dst[t] = dst[e0 + t];
    __syncthreads();

    const int seg  = t >> 5;
    const int lane = t & 31;
    const int j0 = s_start[seg];
    const int j1 = s_start[seg + 1];

    float a0 = 0.f, a1 = 0.f, a2 = 0.f, a3 = 0.f;
    for (int j = j0; j < j1; j++) {
        const int4 m = s_meta[j];               // one LDS.128, warp-uniform
        const float c = __int_as_float(m.z);
        const float* p1 = (const float*)((const char*)s_x1 + m.x) + lane;
        const float* p2 = (const float*)((const char*)s_x2 + m.y) + lane;
        // Tiles at fixed 512-float strides -> immediate-offset LDS, conflict-free.
        a0 = fmaf(c * p1[0 * OP_SIZE], p2[0 * OP_SIZE], a0);
        a1 = fmaf(c * p1[1 * OP_SIZE], p2[1 * OP_SIZE], a1);
        a2 = fmaf(c * p1[2 * OP_SIZE], p2[2 * OP_SIZE], a2);
        a3 = fmaf(c * p1[3 * OP_SIZE], p2[3 * OP_SIZE], a3);
    }

    if (j1 > j0) {
        // Unused return -> no-return global reduction, coalesced 128B per warp.
        atomicAdd(&out[(size_t)s_dst[0] * OP_SIZE + t], a0);
        atomicAdd(&out[(size_t)s_dst[1] * OP_SIZE + t], a1);
        atomicAdd(&out[(size_t)s_dst[2] * OP_SIZE + t], a2);
        atomicAdd(&out[(size_t)s_dst[3] * OP_SIZE + t], a3);
    }
    // Segments with no paths contribute exactly 0 -> output stays at memset 0.
}

extern "C" void kernel_launch(void* const* d_in, const int* in_sizes, int n_in,
                              void* d_out, int out_size) {
    const float* x_nodes      = (const float*)d_in[0];
    const float* x_edges      = (const float*)d_in[1];
    const float* path_coeffs  = (const float*)d_in[2];
    const int*   src          = (const int*)d_in[3];
    const int*   dst          = (const int*)d_in[4];
    const int*   path_indices = (const int*)d_in[5];
    float* out = (float*)d_out;

    // Output is poisoned 0xAA by the harness; zero it (graph-capturable).
    cudaMemsetAsync(out, 0, (size_t)N_NODES * OP_SIZE * sizeof(float));

    prep_paths_kernel<<<1, 32>>>(path_indices, path_coeffs);

    seg_poly_kernel<<<N_EDGES / EPB, OP_SIZE>>>(x_nodes, x_edges, src, dst, out);
}